// round 12
// baseline (speedup 1.0000x reference)
#include <cuda_runtime.h>
#include <cuda_fp16.h>
#include <cstdint>

#define ROWS   81920
#define NCOLS  4096
#define KG     48               // GEMM K: f1 level only (45 real + 3 pad)
#define ROWB   96               // g_Y row bytes (48 fp16)
#define HROWB  192              // g_Hh row bytes (96 fp16: f1|f2|pad)
#define SSTR   112              // smem row stride (7 x 16B -> conflict-free ldmatrix)
#define TPC    8
#define MSLOTS 80
#define NT     32               // 4096 / 128 N-tiles

// SMEM: B tile 128x112 = 14336 ; A double buffer 2 x 14336
#define SM_B   0
#define SM_A0  14336
#define SM_A1  28672
#define SM_TOT 43008

__device__ __align__(16) __half        g_Y [(size_t)ROWS * KG];    // 7.9 MB (f1 signs)
__device__ __align__(16) __half        g_Hh[(size_t)NCOLS * 96];   // 786 KB: [n][f1(45)0(3)f2(45)0(3)]
__device__ unsigned long long          g_mask[ROWS];               // 45-bit sign masks
__device__ unsigned long long          g_p1[(size_t)ROWS * NT];    // per (row,ntile) top-1
__device__ unsigned long long          g_p2[(size_t)ROWS * NT];    // per (row,ntile) top-2
__device__ int                         g_bbits;                    // max_col sum|f2| (float bits)

// ---------------- helpers ----------------
__device__ __forceinline__ uint32_t smem_u32(const void* p) {
    uint32_t a;
    asm("{ .reg .u64 t; cvta.to.shared.u64 t, %1; cvt.u32.u64 %0, t; }" : "=r"(a) : "l"(p));
    return a;
}
__device__ __forceinline__ void cpasync16(uint32_t dst, const void* src) {
    asm volatile("cp.async.cg.shared.global [%0], [%1], 16;" :: "r"(dst), "l"(src) : "memory");
}
#define CP_COMMIT() asm volatile("cp.async.commit_group;" ::: "memory")
#define CP_WAIT0()  asm volatile("cp.async.wait_group 0;" ::: "memory")

#define LDX4(d, addr)                                                              \
    asm volatile("ldmatrix.sync.aligned.m8n8.x4.shared.b16 {%0,%1,%2,%3}, [%4];"   \
        : "=r"((d)[0]), "=r"((d)[1]), "=r"((d)[2]), "=r"((d)[3]) : "r"(addr))

#define MMA(c, a, b0, b1)                                                          \
    asm volatile("mma.sync.aligned.m16n8k16.row.col.f32.f16.f16.f32 "              \
        "{%0,%1,%2,%3}, {%4,%5,%6,%7}, {%8,%9}, {%0,%1,%2,%3};"                    \
        : "+f"((c)[0]), "+f"((c)[1]), "+f"((c)[2]), "+f"((c)[3])                   \
        : "r"((a)[0]), "r"((a)[1]), "r"((a)[2]), "r"((a)[3]), "r"(b0), "r"(b1))

__device__ __forceinline__ unsigned pack_key(float v) {
    unsigned u = __float_as_uint(v);
    return u ^ (unsigned)(((int)u >> 31) | 0x80000000);
}
__device__ __forceinline__ float dec_key(unsigned key) {
    unsigned u = (key & 0x80000000u) ? (key ^ 0x80000000u) : ~key;
    return __uint_as_float(u);
}
__device__ __forceinline__ unsigned long long wmax64(unsigned long long v) {
#pragma unroll
    for (int off = 16; off > 0; off >>= 1) {
        unsigned long long o = __shfl_xor_sync(0xffffffffu, v, off);
        if (o > v) v = o;
    }
    return v;
}

// ---------------------------------------------------------------------------
// K0: zero B_max accumulator
// ---------------------------------------------------------------------------
__global__ void k_zero() { g_bbits = 0; }

// ---------------------------------------------------------------------------
// K1: sign masks -> f1-level Y rows (fp16 ±1, 45 + 3 zeros) + save mask
// ---------------------------------------------------------------------------
__global__ void k_signs(const float* __restrict__ x,
                        const float* __restrict__ S,
                        const float* __restrict__ T)
{
    int i = blockIdx.x * blockDim.x + threadIdx.x;
    if (i >= ROWS) return;
    int token = i / 10, g = i % 10;
    const float* xr = x + (token >> 3) * 480 + (token & 7) * 60;

    unsigned long long mask = 0ull;
#pragma unroll
    for (int cl = 0; cl < 3; cl++) {
        int c = 3 * g + cl;
        float x0 = xr[c * 2 + 0], x1 = xr[c * 2 + 1];
        const float* S0 = S + c * 30;
        const float* S1 = S0 + 15;
        const float* Tc = T + c * 15;
#pragma unroll
        for (int k = 0; k < 15; k++) {
            float y = __fadd_rn(__fmul_rn(x0, S0[k]), __fmul_rn(x1, S1[k]));
            y = __fadd_rn(y, -Tc[k]);
            y = __fadd_rn(y, -1e-4f);
            if (y < 0.f) mask |= 1ull << (cl * 15 + k);
        }
    }
    g_mask[i] = mask;

    uint4* yp = reinterpret_cast<uint4*>(g_Y + (size_t)i * KG);
#pragma unroll
    for (int q = 0; q < 6; q++) {
        unsigned w[4];
#pragma unroll
        for (int e = 0; e < 4; e++) {
            int p0 = q * 8 + e * 2, p1 = p0 + 1;
            unsigned lo = (p0 < 45) ? (0x3C00u | ((unsigned)((mask >> p0) & 1ull) << 15)) : 0u;
            unsigned hi = (p1 < 45) ? (0x3C00u | ((unsigned)((mask >> p1) & 1ull) << 15)) : 0u;
            w[e] = lo | (hi << 16);
        }
        yp[q] = make_uint4(w[0], w[1], w[2], w[3]);
    }
}

// ---------------------------------------------------------------------------
// K2: exact 2-way fp16 split of H -> g_Hh[n][f1|f2], + per-col sum|f2| -> B_max
// ---------------------------------------------------------------------------
__global__ void k_hconv(const float* __restrict__ H)
{
    int n = blockIdx.x * blockDim.x + threadIdx.x;
    if (n >= NCOLS) return;
    __half* row = g_Hh + (size_t)n * 96;
    float bsum = 0.f;
    for (int d = 0; d < 45; d++) {
        float h = H[(size_t)d * NCOLS + n];
        __half f1 = __float2half_rn(h);
        float r1 = h - __half2float(f1);
        __half f2 = __float2half_rn(r1);
        row[d] = f1; row[48 + d] = f2;
        bsum += fabsf(__half2float(f2));
    }
    row[45] = row[46] = row[47] = __float2half_rn(0.f);
    row[93] = row[94] = row[95] = __float2half_rn(0.f);
    atomicMax(&g_bbits, (int)__float_as_uint(bsum));   // bsum >= 0: bits compare as ints
}

// ---------------------------------------------------------------------------
// K3: fp16 mma.sync GEMM, K=48, top-2 per (row, ntile) epilogue.
// grid 2560: ntile = bid & 31 (128 cols), mslot = bid >> 5.
// ---------------------------------------------------------------------------
__device__ __forceinline__ void load_A(uint32_t dst, int grow0, int tid)
{
    const char* src = (const char*)g_Y + (size_t)grow0 * ROWB;
#pragma unroll
    for (int it = 0; it < 3; it++) {
        int c = tid + it * 256;                  // 768 chunks: 128 rows x 6
        int r = c / 6, kc = c - r * 6;
        cpasync16(dst + (uint32_t)(r * SSTR + kc * 16), src + (size_t)r * ROWB + kc * 16);
    }
}

__global__ void __launch_bounds__(256, 2) k_gemm()
{
    extern __shared__ char smem[];
    __shared__ unsigned long long win1[128][2], win2[128][2];
    uint32_t sb = smem_u32(smem);
    const int tid = threadIdx.x, wid = tid >> 5, lane = tid & 31;
    const int ntile = blockIdx.x & 31;
    const int mslot = blockIdx.x >> 5;
    const int wm = wid >> 1, wn = wid & 1;

    // B tile: 128 n-rows x 48 k (f1 only)
    {
        const char* hb = (const char*)g_Hh + (size_t)(ntile * 128) * HROWB;
#pragma unroll
        for (int it = 0; it < 3; it++) {
            int c = tid + it * 256;
            int r = c / 6, kc = c - r * 6;
            cpasync16(sb + SM_B + (uint32_t)(r * SSTR + kc * 16), hb + (size_t)r * HROWB + kc * 16);
        }
    }
    load_A(sb + SM_A0, mslot * TPC * 128, tid);
    CP_COMMIT();

    const int j = lane >> 3, lr = lane & 7;
    const uint32_t aoff = (uint32_t)((wm * 32 + (j & 1) * 8 + lr) * SSTR + (j >> 1) * 16);
    const uint32_t boff = sb + SM_B + (uint32_t)((wn * 64 + (j >> 1) * 8 + lr) * SSTR + (j & 1) * 16);
    const int lq = lane & 3, lrow = lane >> 2;

    for (int i = 0; i < TPC; i++) {
        const int b = i & 1;
        CP_WAIT0();
        __syncthreads();
        if (i < TPC - 1) {
            load_A(sb + (b ? SM_A0 : SM_A1), (mslot * TPC + i + 1) * 128, tid);
            CP_COMMIT();
        }

        const uint32_t abase = sb + (b ? SM_A1 : SM_A0) + aoff;
        float acc[2][8][4];
#pragma unroll
        for (int mb = 0; mb < 2; mb++)
#pragma unroll
            for (int nb = 0; nb < 8; nb++)
#pragma unroll
                for (int e = 0; e < 4; e++) acc[mb][nb][e] = 0.f;

#pragma unroll
        for (int ks = 0; ks < 3; ks++) {
            uint32_t a0[4], a1[4];
            LDX4(a0, abase + ks * 32);
            LDX4(a1, abase + ks * 32 + 16 * SSTR);
#pragma unroll
            for (int n16 = 0; n16 < 4; n16++) {
                uint32_t bb[4];
                LDX4(bb, boff + (uint32_t)(n16 * 16 * SSTR) + ks * 32);
                MMA(acc[0][2 * n16],     a0, bb[0], bb[1]);
                MMA(acc[1][2 * n16],     a1, bb[0], bb[1]);
                MMA(acc[0][2 * n16 + 1], a0, bb[2], bb[3]);
                MMA(acc[1][2 * n16 + 1], a1, bb[2], bb[3]);
            }
        }

        // Epilogue: top-2 per row over this warp's 64 cols, first-index ties
        const int colbase = ntile * 128 + wn * 64 + 2 * lq;
#pragma unroll
        for (int mb = 0; mb < 2; mb++) {
#pragma unroll
            for (int h = 0; h < 2; h++) {
                unsigned long long p1 = 0, p2 = 0;
#pragma unroll
                for (int nb = 0; nb < 8; nb++) {
#pragma unroll
                    for (int t = 0; t < 2; t++) {
                        float v = acc[mb][nb][2 * h + t];
                        unsigned c = (unsigned)(colbase + nb * 8 + t);
                        unsigned long long pk =
                            ((unsigned long long)pack_key(v) << 32)
                            | (unsigned long long)(4095u - c);
                        if (pk > p1) { p2 = p1; p1 = pk; }
                        else if (pk > p2) { p2 = pk; }
                    }
                }
#pragma unroll
                for (int off = 1; off < 4; off <<= 1) {
                    unsigned long long o1 = __shfl_xor_sync(0xffffffffu, p1, off);
                    unsigned long long o2 = __shfl_xor_sync(0xffffffffu, p2, off);
                    unsigned long long lo = (p1 < o1) ? p1 : o1;
                    p1 = (p1 > o1) ? p1 : o1;
                    p2 = (o2 > p2) ? o2 : p2;
                    p2 = (lo > p2) ? lo : p2;
                }
                if (lq == 0) {
                    int rl = wm * 32 + mb * 16 + h * 8 + lrow;
                    win1[rl][wn] = p1; win2[rl][wn] = p2;
                }
            }
        }
        __syncthreads();
        if (tid < 128) {
            unsigned long long a1 = win1[tid][0], a2 = win2[tid][0];
            unsigned long long b1 = win1[tid][1], b2 = win2[tid][1];
            unsigned long long t1 = (a1 > b1) ? a1 : b1;
            unsigned long long lo = (a1 < b1) ? a1 : b1;
            unsigned long long t2 = (a2 > b2) ? a2 : b2;
            t2 = (lo > t2) ? lo : t2;
            size_t idx = (size_t)((mslot * TPC + i) * 128 + tid) * NT + ntile;
            g_p1[idx] = t1; g_p2[idx] = t2;
        }
    }
}

// ---------------------------------------------------------------------------
// K4: certify-or-refine merge + LUT gather. One warp per row.
// ---------------------------------------------------------------------------
__global__ void k_merge(const float* __restrict__ LUT, float2* __restrict__ out)
{
    __shared__ unsigned short cands[8][64];
    int wg   = (blockIdx.x * blockDim.x + threadIdx.x) >> 5;
    int lane = threadIdx.x & 31;
    int wslot = (threadIdx.x >> 5);
    if (wg >= ROWS) return;

    unsigned long long t1 = g_p1[(size_t)wg * NT + lane];
    unsigned long long t2 = g_p2[(size_t)wg * NT + lane];

    unsigned long long M1 = wmax64(t1);
    unsigned long long u  = (t1 == M1) ? t2 : t1;   // global #2 is covered by this set
    unsigned long long M2 = wmax64(u);

    float s_w = dec_key((unsigned)(M1 >> 32));
    float s_2 = dec_key((unsigned)(M2 >> 32));
    float thr = 2.f * __uint_as_float((unsigned)g_bbits) + 1e-3f;

    const float2* l2 = reinterpret_cast<const float2*>(LUT);
    int g = wg % 10;

    if (s_w - s_2 > thr) {                           // certified
        if (lane == 0) {
            int col = 4095 - (int)(unsigned)M1;
            out[wg] = l2[(size_t)g * NCOLS + col];
        }
        return;
    }

    // Refine: gather candidate columns within the window, rescore with f1+f2
    float lim = s_w - thr;
    bool q1 = dec_key((unsigned)(t1 >> 32)) >= lim;
    bool q2 = dec_key((unsigned)(t2 >> 32)) >= lim;
    unsigned b1 = __ballot_sync(0xffffffffu, q1);
    unsigned b2 = __ballot_sync(0xffffffffu, q2);
    int n1 = __popc(b1);
    unsigned lmask = (1u << lane) - 1u;
    if (q1) cands[wslot][__popc(b1 & lmask)] = (unsigned short)(4095 - (int)(unsigned)t1);
    if (q2) cands[wslot][n1 + __popc(b2 & lmask)] = (unsigned short)(4095 - (int)(unsigned)t2);
    int nc = n1 + __popc(b2);
    __syncwarp();

    unsigned long long mask = g_mask[wg];
    unsigned long long best = 0;
    for (int k = lane; k < nc; k += 32) {
        int col = cands[wslot][k];
        const __half* hr = g_Hh + (size_t)col * 96;
        float s = 0.f;
#pragma unroll
        for (int d = 0; d < 45; d++) {
            float sgn = ((mask >> d) & 1ull) ? -1.f : 1.f;
            s += sgn * (__half2float(hr[d]) + __half2float(hr[48 + d]));
        }
        unsigned long long pk = ((unsigned long long)pack_key(s) << 32)
                              | (unsigned long long)(4095u - (unsigned)col);
        if (pk > best) best = pk;
    }
    best = wmax64(best);
    if (lane == 0) {
        int col = 4095 - (int)(unsigned)best;
        out[wg] = l2[(size_t)g * NCOLS + col];
    }
}

// ---------------------------------------------------------------------------
extern "C" void kernel_launch(void* const* d_in, const int* in_sizes, int n_in,
                              void* d_out, int out_size)
{
    const float* x   = (const float*)d_in[0];
    const float* S   = (const float*)d_in[1];
    const float* T   = (const float*)d_in[2];
    const float* H   = (const float*)d_in[3];
    const float* LUT = (const float*)d_in[4];
    (void)in_sizes; (void)n_in; (void)out_size;

    cudaFuncSetAttribute(k_gemm, cudaFuncAttributeMaxDynamicSharedMemorySize, SM_TOT);

    k_zero <<<1, 1>>>();
    k_signs<<<(ROWS + 255) / 256, 256>>>(x, S, T);
    k_hconv<<<NCOLS / 256, 256>>>(H);
    k_gemm <<<MSLOTS * NT, 256, SM_TOT>>>();
    k_merge<<<(ROWS * 32 + 255) / 256, 256>>>(LUT, (float2*)d_out);
}

// round 13
// speedup vs baseline: 1.7587x; 1.7587x over previous
#include <cuda_runtime.h>
#include <cuda_fp16.h>
#include <cstdint>

#define ROWS   81920
#define NCOLS  4096
#define KG     48               // GEMM K: f1 level only (45 real + 3 pad)
#define ROWB   96               // g_Y row bytes (48 fp16)
#define HROWB  192              // g_Hh row bytes (96 fp16: f1|f2)
#define SSTR   112              // smem row stride (7 x 16B -> conflict-free ldmatrix)
#define TPC    8
#define MSLOTS 80
#define NT     32               // 4096 / 128 N-tiles

// SMEM: B tile 128x112 = 14336 ; A double buffer 2 x 14336
#define SM_B   0
#define SM_A0  14336
#define SM_A1  28672
#define SM_TOT 43008

__device__ __align__(16) __half        g_Y [(size_t)ROWS * KG];    // 7.9 MB (f1 signs)
__device__ __align__(16) __half        g_Hh[(size_t)NCOLS * 96];   // 786 KB: [n][f1(45)0(3)f2(45)0(3)]
__device__ unsigned long long          g_mask[ROWS];               // 45-bit sign masks
__device__ unsigned long long          g_p12[(size_t)ROWS * NT];   // per (row,ntile): top1<<32 | top2
__device__ int                         g_bbits;                    // max_col sum|f2| (float bits)

// ---------------- helpers ----------------
__device__ __forceinline__ uint32_t smem_u32(const void* p) {
    uint32_t a;
    asm("{ .reg .u64 t; cvta.to.shared.u64 t, %1; cvt.u32.u64 %0, t; }" : "=r"(a) : "l"(p));
    return a;
}
__device__ __forceinline__ void cpasync16(uint32_t dst, const void* src) {
    asm volatile("cp.async.cg.shared.global [%0], [%1], 16;" :: "r"(dst), "l"(src) : "memory");
}
#define CP_COMMIT() asm volatile("cp.async.commit_group;" ::: "memory")
#define CP_WAIT0()  asm volatile("cp.async.wait_group 0;" ::: "memory")

#define LDX4(d, addr)                                                              \
    asm volatile("ldmatrix.sync.aligned.m8n8.x4.shared.b16 {%0,%1,%2,%3}, [%4];"   \
        : "=r"((d)[0]), "=r"((d)[1]), "=r"((d)[2]), "=r"((d)[3]) : "r"(addr))

#define MMA(c, a, b0, b1)                                                          \
    asm volatile("mma.sync.aligned.m16n8k16.row.col.f32.f16.f16.f32 "              \
        "{%0,%1,%2,%3}, {%4,%5,%6,%7}, {%8,%9}, {%0,%1,%2,%3};"                    \
        : "+f"((c)[0]), "+f"((c)[1]), "+f"((c)[2]), "+f"((c)[3])                   \
        : "r"((a)[0]), "r"((a)[1]), "r"((a)[2]), "r"((a)[3]), "r"(b0), "r"(b1))

__device__ __forceinline__ unsigned pack_key(float v) {          // full monotone (refine only)
    unsigned u = __float_as_uint(v);
    return u ^ (unsigned)(((int)u >> 31) | 0x80000000);
}
__device__ __forceinline__ unsigned wmax32(unsigned v) {
#pragma unroll
    for (int off = 16; off > 0; off >>= 1)
        v = umax(v, __shfl_xor_sync(0xffffffffu, v, off));
    return v;
}
__device__ __forceinline__ unsigned long long wmax64(unsigned long long v) {
#pragma unroll
    for (int off = 16; off > 0; off >>= 1) {
        unsigned long long o = __shfl_xor_sync(0xffffffffu, v, off);
        if (o > v) v = o;
    }
    return v;
}
__device__ __forceinline__ float dec_u32key(unsigned k) {        // lower bound of score
    return __uint_as_float(k & 0xFFFFFF80u) - 512.f;
}

// ---------------------------------------------------------------------------
__global__ void k_zero() { g_bbits = 0; }

// ---------------------------------------------------------------------------
// K1: sign masks -> f1-level Y rows (fp16 ±1, 45 + 3 zeros) + save mask
// ---------------------------------------------------------------------------
__global__ void k_signs(const float* __restrict__ x,
                        const float* __restrict__ S,
                        const float* __restrict__ T)
{
    int i = blockIdx.x * blockDim.x + threadIdx.x;
    if (i >= ROWS) return;
    int token = i / 10, g = i % 10;
    const float* xr = x + (token >> 3) * 480 + (token & 7) * 60;

    unsigned long long mask = 0ull;
#pragma unroll
    for (int cl = 0; cl < 3; cl++) {
        int c = 3 * g + cl;
        float x0 = xr[c * 2 + 0], x1 = xr[c * 2 + 1];
        const float* S0 = S + c * 30;
        const float* S1 = S0 + 15;
        const float* Tc = T + c * 15;
#pragma unroll
        for (int k = 0; k < 15; k++) {
            float y = __fadd_rn(__fmul_rn(x0, S0[k]), __fmul_rn(x1, S1[k]));
            y = __fadd_rn(y, -Tc[k]);
            y = __fadd_rn(y, -1e-4f);
            if (y < 0.f) mask |= 1ull << (cl * 15 + k);
        }
    }
    g_mask[i] = mask;

    uint4* yp = reinterpret_cast<uint4*>(g_Y + (size_t)i * KG);
#pragma unroll
    for (int q = 0; q < 6; q++) {
        unsigned w[4];
#pragma unroll
        for (int e = 0; e < 4; e++) {
            int p0 = q * 8 + e * 2, p1 = p0 + 1;
            unsigned lo = (p0 < 45) ? (0x3C00u | ((unsigned)((mask >> p0) & 1ull) << 15)) : 0u;
            unsigned hi = (p1 < 45) ? (0x3C00u | ((unsigned)((mask >> p1) & 1ull) << 15)) : 0u;
            w[e] = lo | (hi << 16);
        }
        yp[q] = make_uint4(w[0], w[1], w[2], w[3]);
    }
}

// ---------------------------------------------------------------------------
// K2: exact 2-way fp16 split of H + per-col sum|f2| -> B_max
// ---------------------------------------------------------------------------
__global__ void k_hconv(const float* __restrict__ H)
{
    int n = blockIdx.x * blockDim.x + threadIdx.x;
    if (n >= NCOLS) return;
    __half* row = g_Hh + (size_t)n * 96;
    float bsum = 0.f;
    for (int d = 0; d < 45; d++) {
        float h = H[(size_t)d * NCOLS + n];
        __half f1 = __float2half_rn(h);
        float r1 = h - __half2float(f1);
        __half f2 = __float2half_rn(r1);
        row[d] = f1; row[48 + d] = f2;
        bsum += fabsf(__half2float(f2));
    }
    row[45] = row[46] = row[47] = __float2half_rn(0.f);
    row[93] = row[94] = row[95] = __float2half_rn(0.f);
    atomicMax(&g_bbits, (int)__float_as_uint(bsum));   // bsum >= 0: bits compare as ints
}

// ---------------------------------------------------------------------------
// K3: fp16 mma.sync GEMM, K=48, ALU-minimal u32 top-2 epilogue.
// grid 2560: ntile = bid & 31 (128 cols), mslot = bid >> 5.
// ---------------------------------------------------------------------------
__device__ __forceinline__ void load_A(uint32_t dst, int grow0, int tid)
{
    const char* src = (const char*)g_Y + (size_t)grow0 * ROWB;
#pragma unroll
    for (int it = 0; it < 3; it++) {
        int c = tid + it * 256;                  // 768 chunks: 128 rows x 6
        int r = c / 6, kc = c - r * 6;
        cpasync16(dst + (uint32_t)(r * SSTR + kc * 16), src + (size_t)r * ROWB + kc * 16);
    }
}

__global__ void __launch_bounds__(256, 2) k_gemm()
{
    extern __shared__ char smem[];
    __shared__ unsigned win1[128][2], win2[128][2];
    uint32_t sb = smem_u32(smem);
    const int tid = threadIdx.x, wid = tid >> 5, lane = tid & 31;
    const int ntile = blockIdx.x & 31;
    const int mslot = blockIdx.x >> 5;
    const int wm = wid >> 1, wn = wid & 1;

    // B tile: 128 n-rows x 48 k (f1 only)
    {
        const char* hb = (const char*)g_Hh + (size_t)(ntile * 128) * HROWB;
#pragma unroll
        for (int it = 0; it < 3; it++) {
            int c = tid + it * 256;
            int r = c / 6, kc = c - r * 6;
            cpasync16(sb + SM_B + (uint32_t)(r * SSTR + kc * 16), hb + (size_t)r * HROWB + kc * 16);
        }
    }
    load_A(sb + SM_A0, mslot * TPC * 128, tid);
    CP_COMMIT();

    const int j = lane >> 3, lr = lane & 7;
    const uint32_t aoff = (uint32_t)((wm * 32 + (j & 1) * 8 + lr) * SSTR + (j >> 1) * 16);
    const uint32_t boff = sb + SM_B + (uint32_t)((wn * 64 + (j >> 1) * 8 + lr) * SSTR + (j & 1) * 16);
    const int lq = lane & 3, lrow = lane >> 2;
    const unsigned colc0 = (unsigned)(127 - (wn * 64 + 2 * lq));   // complemented local col base

    for (int i = 0; i < TPC; i++) {
        const int b = i & 1;
        CP_WAIT0();
        __syncthreads();
        if (i < TPC - 1) {
            load_A(sb + (b ? SM_A0 : SM_A1), (mslot * TPC + i + 1) * 128, tid);
            CP_COMMIT();
        }

        const uint32_t abase = sb + (b ? SM_A1 : SM_A0) + aoff;
        float acc[2][8][4];
#pragma unroll
        for (int mb = 0; mb < 2; mb++)
#pragma unroll
            for (int nb = 0; nb < 8; nb++)
#pragma unroll
                for (int e = 0; e < 4; e++) acc[mb][nb][e] = 0.f;

#pragma unroll
        for (int ks = 0; ks < 3; ks++) {
            uint32_t a0[4], a1[4];
            LDX4(a0, abase + ks * 32);
            LDX4(a1, abase + ks * 32 + 16 * SSTR);
#pragma unroll
            for (int n16 = 0; n16 < 4; n16++) {
                uint32_t bb[4];
                LDX4(bb, boff + (uint32_t)(n16 * 16 * SSTR) + ks * 32);
                MMA(acc[0][2 * n16],     a0, bb[0], bb[1]);
                MMA(acc[1][2 * n16],     a1, bb[0], bb[1]);
                MMA(acc[0][2 * n16 + 1], a0, bb[2], bb[3]);
                MMA(acc[1][2 * n16 + 1], a1, bb[2], bb[3]);
            }
        }

        // Epilogue: u32-key top-2 per row over this warp's 64 columns.
        // key = float_bits(s + 512)[31:7] | (127 - col_local)  — monotone, first-index ties.
#pragma unroll
        for (int mb = 0; mb < 2; mb++) {
#pragma unroll
            for (int h = 0; h < 2; h++) {
                unsigned t1 = 0, t2 = 0;
#pragma unroll
                for (int nb = 0; nb < 8; nb++) {
#pragma unroll
                    for (int t = 0; t < 2; t++) {
                        unsigned bits = __float_as_uint(acc[mb][nb][2 * h + t] + 512.f);
                        unsigned key  = (bits & 0xFFFFFF80u) | (colc0 - nb * 8 - t);
                        unsigned n1 = umax(t1, key);
                        t2 = umax(t2, umin(t1, key));
                        t1 = n1;
                    }
                }
#pragma unroll
                for (int off = 1; off < 4; off <<= 1) {
                    unsigned o1 = __shfl_xor_sync(0xffffffffu, t1, off);
                    unsigned o2 = __shfl_xor_sync(0xffffffffu, t2, off);
                    t2 = umax(umax(t2, o2), umin(t1, o1));
                    t1 = umax(t1, o1);
                }
                if (lq == 0) {
                    int rl = wm * 32 + mb * 16 + h * 8 + lrow;
                    win1[rl][wn] = t1; win2[rl][wn] = t2;
                }
            }
        }
        __syncthreads();
        if (tid < 128) {
            unsigned a1 = win1[tid][0], a2 = win2[tid][0];
            unsigned b1 = win1[tid][1], b2 = win2[tid][1];
            unsigned T1 = umax(a1, b1);
            unsigned T2 = umax(umin(a1, b1), umax(a2, b2));
            g_p12[(size_t)((mslot * TPC + i) * 128 + tid) * NT + ntile] =
                ((unsigned long long)T1 << 32) | (unsigned long long)T2;
        }
    }
}

// ---------------------------------------------------------------------------
// K4: certify-or-refine merge + LUT gather. One warp per row (lane = ntile).
// ---------------------------------------------------------------------------
__global__ void k_merge(const float* __restrict__ LUT, float2* __restrict__ out)
{
    __shared__ unsigned short cands[8][64];
    int wg    = (blockIdx.x * blockDim.x + threadIdx.x) >> 5;
    int lane  = threadIdx.x & 31;
    int wslot = (threadIdx.x >> 5) & 7;
    if (wg >= ROWS) return;

    unsigned long long v = g_p12[(size_t)wg * NT + lane];
    unsigned t1 = (unsigned)(v >> 32), t2 = (unsigned)v;

    unsigned M1 = wmax32(t1);
    unsigned M2 = wmax32((t1 == M1) ? t2 : t1);   // covers global #2

    float val1 = dec_u32key(M1);
    float val2 = dec_u32key(M2);
    float thr  = 2.f * __uint_as_float((unsigned)g_bbits) + 0.03f;

    const float2* l2 = reinterpret_cast<const float2*>(LUT);
    int g = wg % 10;

    if (val1 - val2 > thr) {                      // certified winner
        unsigned ball = __ballot_sync(0xffffffffu, t1 == M1);
        if (lane == 0) {
            int wl  = __ffs(ball) - 1;            // lowest tile on cross-tile key tie
            int col = wl * 128 + 127 - (int)(M1 & 0x7Fu);
            out[wg] = l2[(size_t)g * NCOLS + col];
        }
        return;
    }

    // Refine: rescore all candidate columns within the window exactly (f1+f2)
    float lim = val1 - thr;
    bool q1 = dec_u32key(t1) >= lim;
    bool q2 = dec_u32key(t2) >= lim;
    unsigned b1 = __ballot_sync(0xffffffffu, q1);
    unsigned b2 = __ballot_sync(0xffffffffu, q2);
    int n1 = __popc(b1);
    unsigned lmask = (1u << lane) - 1u;
    if (q1) cands[wslot][__popc(b1 & lmask)]      = (unsigned short)(lane * 128 + 127 - (int)(t1 & 0x7Fu));
    if (q2) cands[wslot][n1 + __popc(b2 & lmask)] = (unsigned short)(lane * 128 + 127 - (int)(t2 & 0x7Fu));
    int nc = n1 + __popc(b2);
    __syncwarp();

    unsigned long long mask = g_mask[wg];
    unsigned long long best = 0;
    for (int k = lane; k < nc; k += 32) {
        int col = cands[wslot][k];
        const __half* hr = g_Hh + (size_t)col * 96;
        float s = 0.f;
#pragma unroll
        for (int d = 0; d < 45; d++) {
            float sgn = ((mask >> d) & 1ull) ? -1.f : 1.f;
            s += sgn * (__half2float(hr[d]) + __half2float(hr[48 + d]));
        }
        unsigned long long pk = ((unsigned long long)pack_key(s) << 32)
                              | (unsigned long long)(4095u - (unsigned)col);
        if (pk > best) best = pk;
    }
    best = wmax64(best);
    if (lane == 0) {
        int col = 4095 - (int)(unsigned)best;
        out[wg] = l2[(size_t)g * NCOLS + col];
    }
}

// ---------------------------------------------------------------------------
extern "C" void kernel_launch(void* const* d_in, const int* in_sizes, int n_in,
                              void* d_out, int out_size)
{
    const float* x   = (const float*)d_in[0];
    const float* S   = (const float*)d_in[1];
    const float* T   = (const float*)d_in[2];
    const float* H   = (const float*)d_in[3];
    const float* LUT = (const float*)d_in[4];
    (void)in_sizes; (void)n_in; (void)out_size;

    cudaFuncSetAttribute(k_gemm, cudaFuncAttributeMaxDynamicSharedMemorySize, SM_TOT);

    k_zero <<<1, 1>>>();
    k_signs<<<(ROWS + 255) / 256, 256>>>(x, S, T);
    k_hconv<<<NCOLS / 256, 256>>>(H);
    k_gemm <<<MSLOTS * NT, 256, SM_TOT>>>();
    k_merge<<<(ROWS * 32 + 255) / 256, 256>>>(LUT, (float2*)d_out);
}

// round 14
// speedup vs baseline: 2.0062x; 1.1408x over previous
#include <cuda_runtime.h>
#include <cuda_fp16.h>
#include <cstdint>

#define ROWS   81920
#define NCOLS  4096
#define KG     48               // GEMM K: f1 level only (45 real + 3 pad)
#define ROWB   96               // g_Y row bytes (48 fp16)
#define HROWB  192              // g_Hh row bytes (96 fp16: f1|f2)
#define SSTR   112              // smem row stride (7 x 16B -> conflict-free ldmatrix)
#define TPC    8
#define MSLOTS 80
#define NT     32               // 4096 / 128 N-tiles

// SMEM: B tile 128x112 = 14336 ; A double buffer 2 x 14336
#define SM_B   0
#define SM_A0  14336
#define SM_A1  28672
#define SM_TOT 43008

__device__ __align__(16) __half        g_Y [(size_t)ROWS * KG];    // 7.9 MB (f1 signs)
__device__ __align__(16) __half        g_Hh[(size_t)NCOLS * 96];   // 786 KB: [n][f1(45)0(3)f2(45)0(3)]
__device__ unsigned long long          g_mask[ROWS];               // 45-bit sign masks
__device__ unsigned long long          g_p12[(size_t)ROWS * NT];   // per (row,ntile): top1<<32 | top2
__device__ int                         g_bbits;                    // max_col sum|f2| (float bits)

// ---------------- helpers ----------------
__device__ __forceinline__ uint32_t smem_u32(const void* p) {
    uint32_t a;
    asm("{ .reg .u64 t; cvta.to.shared.u64 t, %1; cvt.u32.u64 %0, t; }" : "=r"(a) : "l"(p));
    return a;
}
__device__ __forceinline__ void cpasync16(uint32_t dst, const void* src) {
    asm volatile("cp.async.cg.shared.global [%0], [%1], 16;" :: "r"(dst), "l"(src) : "memory");
}
#define CP_COMMIT() asm volatile("cp.async.commit_group;" ::: "memory")
#define CP_WAIT0()  asm volatile("cp.async.wait_group 0;" ::: "memory")

#define LDX4(d, addr)                                                              \
    asm volatile("ldmatrix.sync.aligned.m8n8.x4.shared.b16 {%0,%1,%2,%3}, [%4];"   \
        : "=r"((d)[0]), "=r"((d)[1]), "=r"((d)[2]), "=r"((d)[3]) : "r"(addr))

#define MMA(c, a, b0, b1)                                                          \
    asm volatile("mma.sync.aligned.m16n8k16.row.col.f32.f16.f16.f32 "              \
        "{%0,%1,%2,%3}, {%4,%5,%6,%7}, {%8,%9}, {%0,%1,%2,%3};"                    \
        : "+f"((c)[0]), "+f"((c)[1]), "+f"((c)[2]), "+f"((c)[3])                   \
        : "r"((a)[0]), "r"((a)[1]), "r"((a)[2]), "r"((a)[3]), "r"(b0), "r"(b1))

__device__ __forceinline__ unsigned pack_key(float v) {          // full monotone (refine only)
    unsigned u = __float_as_uint(v);
    return u ^ (unsigned)(((int)u >> 31) | 0x80000000);
}
__device__ __forceinline__ unsigned wmax32(unsigned v) {
#pragma unroll
    for (int off = 16; off > 0; off >>= 1)
        v = umax(v, __shfl_xor_sync(0xffffffffu, v, off));
    return v;
}
__device__ __forceinline__ unsigned long long wmax64(unsigned long long v) {
#pragma unroll
    for (int off = 16; off > 0; off >>= 1) {
        unsigned long long o = __shfl_xor_sync(0xffffffffu, v, off);
        if (o > v) v = o;
    }
    return v;
}
__device__ __forceinline__ float dec_u32key(unsigned k) {        // lower bound of score
    return __uint_as_float(k & 0xFFFFFF80u) - 512.f;
}

// ---------------------------------------------------------------------------
__global__ void k_zero() { g_bbits = 0; }

// ---------------------------------------------------------------------------
// K1: sign masks -> f1-level Y rows (fp16 ±1, 45 + 3 zeros) + save mask
// ---------------------------------------------------------------------------
__global__ void k_signs(const float* __restrict__ x,
                        const float* __restrict__ S,
                        const float* __restrict__ T)
{
    int i = blockIdx.x * blockDim.x + threadIdx.x;
    if (i >= ROWS) return;
    int token = i / 10, g = i % 10;
    const float* xr = x + (token >> 3) * 480 + (token & 7) * 60;

    unsigned long long mask = 0ull;
#pragma unroll
    for (int cl = 0; cl < 3; cl++) {
        int c = 3 * g + cl;
        float x0 = xr[c * 2 + 0], x1 = xr[c * 2 + 1];
        const float* S0 = S + c * 30;
        const float* S1 = S0 + 15;
        const float* Tc = T + c * 15;
#pragma unroll
        for (int k = 0; k < 15; k++) {
            float y = __fadd_rn(__fmul_rn(x0, S0[k]), __fmul_rn(x1, S1[k]));
            y = __fadd_rn(y, -Tc[k]);
            y = __fadd_rn(y, -1e-4f);
            if (y < 0.f) mask |= 1ull << (cl * 15 + k);
        }
    }
    g_mask[i] = mask;

    uint4* yp = reinterpret_cast<uint4*>(g_Y + (size_t)i * KG);
#pragma unroll
    for (int q = 0; q < 6; q++) {
        unsigned w[4];
#pragma unroll
        for (int e = 0; e < 4; e++) {
            int p0 = q * 8 + e * 2, p1 = p0 + 1;
            unsigned lo = (p0 < 45) ? (0x3C00u | ((unsigned)((mask >> p0) & 1ull) << 15)) : 0u;
            unsigned hi = (p1 < 45) ? (0x3C00u | ((unsigned)((mask >> p1) & 1ull) << 15)) : 0u;
            w[e] = lo | (hi << 16);
        }
        yp[q] = make_uint4(w[0], w[1], w[2], w[3]);
    }
}

// ---------------------------------------------------------------------------
// K2: exact 2-way fp16 split of H + per-col sum|f2| -> B_max
// ---------------------------------------------------------------------------
__global__ void k_hconv(const float* __restrict__ H)
{
    int n = blockIdx.x * blockDim.x + threadIdx.x;
    if (n >= NCOLS) return;
    __half* row = g_Hh + (size_t)n * 96;
    float bsum = 0.f;
    for (int d = 0; d < 45; d++) {
        float h = H[(size_t)d * NCOLS + n];
        __half f1 = __float2half_rn(h);
        float r1 = h - __half2float(f1);
        __half f2 = __float2half_rn(r1);
        row[d] = f1; row[48 + d] = f2;
        bsum += fabsf(__half2float(f2));
    }
    row[45] = row[46] = row[47] = __float2half_rn(0.f);
    row[93] = row[94] = row[95] = __float2half_rn(0.f);
    atomicMax(&g_bbits, (int)__float_as_uint(bsum));   // bsum >= 0: bits compare as ints
}

// ---------------------------------------------------------------------------
// K3: fp16 mma.sync GEMM, K=48, 4-slot/score u32 top-2 epilogue.
// grid 2560: ntile = bid & 31 (128 cols), mslot = bid >> 5.
// acc initialized to +512 => accumulators are positive; raw bits monotone.
// key = (bits & ~0x7F) ^ codeB ^ (8nb+t): single LOP3 (XOR==subtract, borrow-free).
// ---------------------------------------------------------------------------
__device__ __forceinline__ void load_A(uint32_t dst, int grow0, int tid)
{
    const char* src = (const char*)g_Y + (size_t)grow0 * ROWB;
#pragma unroll
    for (int it = 0; it < 3; it++) {
        int c = tid + it * 256;                  // 768 chunks: 128 rows x 6
        int r = c / 6, kc = c - r * 6;
        cpasync16(dst + (uint32_t)(r * SSTR + kc * 16), src + (size_t)r * ROWB + kc * 16);
    }
}

__global__ void __launch_bounds__(256, 2) k_gemm()
{
    extern __shared__ char smem[];
    __shared__ unsigned win1[128][2], win2[128][2];
    uint32_t sb = smem_u32(smem);
    const int tid = threadIdx.x, wid = tid >> 5, lane = tid & 31;
    const int ntile = blockIdx.x & 31;
    const int mslot = blockIdx.x >> 5;
    const int wm = wid >> 1, wn = wid & 1;

    // B tile: 128 n-rows x 48 k (f1 only)
    {
        const char* hb = (const char*)g_Hh + (size_t)(ntile * 128) * HROWB;
#pragma unroll
        for (int it = 0; it < 3; it++) {
            int c = tid + it * 256;
            int r = c / 6, kc = c - r * 6;
            cpasync16(sb + SM_B + (uint32_t)(r * SSTR + kc * 16), hb + (size_t)r * HROWB + kc * 16);
        }
    }
    load_A(sb + SM_A0, mslot * TPC * 128, tid);
    CP_COMMIT();

    const int j = lane >> 3, lr = lane & 7;
    const uint32_t aoff = (uint32_t)((wm * 32 + (j & 1) * 8 + lr) * SSTR + (j >> 1) * 16);
    const uint32_t boff = sb + SM_B + (uint32_t)((wn * 64 + (j >> 1) * 8 + lr) * SSTR + (j & 1) * 16);
    const int lq = lane & 3, lrow = lane >> 2;
    const unsigned codeB = (unsigned)(127 - wn * 64 - 2 * lq);     // bits {0,3,4,5} all set

    for (int i = 0; i < TPC; i++) {
        const int b = i & 1;
        CP_WAIT0();
        __syncthreads();
        if (i < TPC - 1) {
            load_A(sb + (b ? SM_A0 : SM_A1), (mslot * TPC + i + 1) * 128, tid);
            CP_COMMIT();
        }

        const uint32_t abase = sb + (b ? SM_A1 : SM_A0) + aoff;
        float acc[2][8][4];
#pragma unroll
        for (int mb = 0; mb < 2; mb++)
#pragma unroll
            for (int nb = 0; nb < 8; nb++)
#pragma unroll
                for (int e = 0; e < 4; e++) acc[mb][nb][e] = 512.f;   // bias in init

#pragma unroll
        for (int ks = 0; ks < 3; ks++) {
            uint32_t a0[4], a1[4];
            LDX4(a0, abase + ks * 32);
            LDX4(a1, abase + ks * 32 + 16 * SSTR);
#pragma unroll
            for (int n16 = 0; n16 < 4; n16++) {
                uint32_t bb[4];
                LDX4(bb, boff + (uint32_t)(n16 * 16 * SSTR) + ks * 32);
                MMA(acc[0][2 * n16],     a0, bb[0], bb[1]);
                MMA(acc[1][2 * n16],     a1, bb[0], bb[1]);
                MMA(acc[0][2 * n16 + 1], a0, bb[2], bb[3]);
                MMA(acc[1][2 * n16 + 1], a1, bb[2], bb[3]);
            }
        }

        // Epilogue: u32-key top-2 per row (4 slots/score: LOP3 + 3 IMNMX)
#pragma unroll
        for (int mb = 0; mb < 2; mb++) {
#pragma unroll
            for (int h = 0; h < 2; h++) {
                unsigned t1 = 0, t2 = 0;
#pragma unroll
                for (int nb = 0; nb < 8; nb++) {
#pragma unroll
                    for (int t = 0; t < 2; t++) {
                        unsigned bits = __float_as_uint(acc[mb][nb][2 * h + t]);
                        unsigned key  = ((bits & 0xFFFFFF80u) ^ codeB) ^ (unsigned)(8 * nb + t);
                        unsigned n1 = umax(t1, key);
                        t2 = umax(t2, umin(t1, key));
                        t1 = n1;
                    }
                }
#pragma unroll
                for (int off = 1; off < 4; off <<= 1) {
                    unsigned o1 = __shfl_xor_sync(0xffffffffu, t1, off);
                    unsigned o2 = __shfl_xor_sync(0xffffffffu, t2, off);
                    t2 = umax(umax(t2, o2), umin(t1, o1));
                    t1 = umax(t1, o1);
                }
                if (lq == 0) {
                    int rl = wm * 32 + mb * 16 + h * 8 + lrow;
                    win1[rl][wn] = t1; win2[rl][wn] = t2;
                }
            }
        }
        __syncthreads();
        if (tid < 128) {
            unsigned a1 = win1[tid][0], a2 = win2[tid][0];
            unsigned b1 = win1[tid][1], b2 = win2[tid][1];
            unsigned T1 = umax(a1, b1);
            unsigned T2 = umax(umin(a1, b1), umax(a2, b2));
            g_p12[(size_t)((mslot * TPC + i) * 128 + tid) * NT + ntile] =
                ((unsigned long long)T1 << 32) | (unsigned long long)T2;
        }
    }
}

// ---------------------------------------------------------------------------
// K4: certify-or-refine merge + LUT gather. One warp per row (lane = ntile).
// ---------------------------------------------------------------------------
__global__ void k_merge(const float* __restrict__ LUT, float2* __restrict__ out)
{
    __shared__ unsigned short cands[8][64];
    int wg    = (blockIdx.x * blockDim.x + threadIdx.x) >> 5;
    int lane  = threadIdx.x & 31;
    int wslot = (threadIdx.x >> 5) & 7;
    if (wg >= ROWS) return;

    unsigned long long v = g_p12[(size_t)wg * NT + lane];
    unsigned t1 = (unsigned)(v >> 32), t2 = (unsigned)v;

    unsigned M1 = wmax32(t1);
    unsigned M2 = wmax32((t1 == M1) ? t2 : t1);   // covers global #2

    float val1 = dec_u32key(M1);
    float val2 = dec_u32key(M2);
    float thr  = 2.f * __uint_as_float((unsigned)g_bbits) + 0.03f;

    const float2* l2 = reinterpret_cast<const float2*>(LUT);
    int g = wg % 10;

    if (val1 - val2 > thr) {                      // certified winner
        unsigned ball = __ballot_sync(0xffffffffu, t1 == M1);
        if (lane == 0) {
            int wl  = __ffs(ball) - 1;            // lowest tile on cross-tile key tie
            int col = wl * 128 + 127 - (int)(M1 & 0x7Fu);
            out[wg] = l2[(size_t)g * NCOLS + col];
        }
        return;
    }

    // Refine: rescore all candidate columns within the window exactly (f1+f2)
    float lim = val1 - thr;
    bool q1 = dec_u32key(t1) >= lim;
    bool q2 = dec_u32key(t2) >= lim;
    unsigned b1 = __ballot_sync(0xffffffffu, q1);
    unsigned b2 = __ballot_sync(0xffffffffu, q2);
    int n1 = __popc(b1);
    unsigned lmask = (1u << lane) - 1u;
    if (q1) cands[wslot][__popc(b1 & lmask)]      = (unsigned short)(lane * 128 + 127 - (int)(t1 & 0x7Fu));
    if (q2) cands[wslot][n1 + __popc(b2 & lmask)] = (unsigned short)(lane * 128 + 127 - (int)(t2 & 0x7Fu));
    int nc = n1 + __popc(b2);
    __syncwarp();

    unsigned long long mask = g_mask[wg];
    unsigned long long best = 0;
    for (int k = lane; k < nc; k += 32) {
        int col = cands[wslot][k];
        const __half* hr = g_Hh + (size_t)col * 96;
        float s = 0.f;
#pragma unroll
        for (int d = 0; d < 45; d++) {
            float sgn = ((mask >> d) & 1ull) ? -1.f : 1.f;
            s += sgn * (__half2float(hr[d]) + __half2float(hr[48 + d]));
        }
        unsigned long long pk = ((unsigned long long)pack_key(s) << 32)
                              | (unsigned long long)(4095u - (unsigned)col);
        if (pk > best) best = pk;
    }
    best = wmax64(best);
    if (lane == 0) {
        int col = 4095 - (int)(unsigned)best;
        out[wg] = l2[(size_t)g * NCOLS + col];
    }
}

// ---------------------------------------------------------------------------
extern "C" void kernel_launch(void* const* d_in, const int* in_sizes, int n_in,
                              void* d_out, int out_size)
{
    const float* x   = (const float*)d_in[0];
    const float* S   = (const float*)d_in[1];
    const float* T   = (const float*)d_in[2];
    const float* H   = (const float*)d_in[3];
    const float* LUT = (const float*)d_in[4];
    (void)in_sizes; (void)n_in; (void)out_size;

    cudaFuncSetAttribute(k_gemm, cudaFuncAttributeMaxDynamicSharedMemorySize, SM_TOT);

    k_zero <<<1, 1>>>();
    k_signs<<<(ROWS + 255) / 256, 256>>>(x, S, T);
    k_hconv<<<NCOLS / 256, 256>>>(H);
    k_gemm <<<MSLOTS * NT, 256, SM_TOT>>>();
    k_merge<<<(ROWS * 32 + 255) / 256, 256>>>(LUT, (float2*)d_out);
}